// round 5
// baseline (speedup 1.0000x reference)
#include <cuda_runtime.h>
#include <cuda_bf16.h>
#include <cmath>
#include <cstdint>
#include <complex>
#include <vector>
#include <algorithm>

#define MAXE 7000
#define MAXN 10000

static __device__ float g_Y0[(size_t)MAXN * 400];

__constant__ unsigned int c_idx[MAXE];
__constant__ float        c_val[MAXE];

// ------------------------- host CG table ----------------------------------
namespace tab {
static int nent = 0;
static unsigned int h_idx[MAXE];
static float h_val[MAXE];
static bool built = false;

static double lf(int n) { return lgamma((double)n + 1.0); }

static double cgc(int l1, int m1, int l2, int m2, int l3, int m3) {
    if (m1 + m2 != m3 || l3 < abs(l1 - l2) || l3 > l1 + l2) return 0.0;
    double pre = 0.5 * (lf(l1+l2-l3) + lf(l1-l2+l3) + lf(-l1+l2+l3) - lf(l1+l2+l3+1)
                 + lf(l1+m1) + lf(l1-m1) + lf(l2+m2) + lf(l2-m2) + lf(l3+m3) + lf(l3-m3));
    int kmin = std::max(0, std::max(l2-l3-m1, l1-l3+m2));
    int kmax = std::min(l1+l2-l3, std::min(l1-m1, l2+m2));
    double s = 0.0;
    for (int k = kmin; k <= kmax; k++) {
        double ln = lf(k) + lf(l1+l2-l3-k) + lf(l1-m1-k) + lf(l2+m2-k)
                  + lf(l3-l2+m1+k) + lf(l3-l1-m2+k);
        s += ((k & 1) ? -1.0 : 1.0) * exp(pre - ln);
    }
    return sqrt(2.0*l3+1.0) * s;
}

static int degof(int lm){ return lm>=16?4: lm>=9?3: lm>=4?2: lm>=1?1:0; }

struct Rent { int path, ic, ia, ib; double v; };
static std::complex<double> Cc[25][25][25];

static void build() {
    if (built) return;
    built = true;
    int pid[5][5][5];
    for (int a=0;a<5;a++)for(int b=0;b<5;b++)for(int c=0;c<5;c++) pid[a][b][c]=-1;
    int np = 0;
    for (int l1=0;l1<=4;l1++)
        for (int l2=0;l2<=4;l2++)
            for (int l3=abs(l1-l2); l3<=std::min(4,l1+l2); l3++)
                pid[l1][l2][l3] = np++;

    for (int l1=0;l1<=4;l1++)
        for (int l2=0;l2<=4;l2++)
            for (int l3=abs(l1-l2); l3<=std::min(4,l1+l2); l3++)
                for (int m1=-l1;m1<=l1;m1++)
                    for (int m2=-l2;m2<=l2;m2++) {
                        int m3 = m1+m2;
                        if (abs(m3) <= l3)
                            Cc[l1*l1+l1+m1][l2*l2+l2+m2][l3*l3+l3+m3] = cgc(l1,m1,l2,m2,l3,m3);
                    }

    const double s2 = 1.0/sqrt(2.0);
    std::complex<double> Uv[25][2]; int Uc[25][2]; int Un[25];
    for (int l=0;l<=4;l++) {
        int off = l*l+l;
        Un[off]=1; Uc[off][0]=off; Uv[off][0]={1,0}; Uc[off][1]=off; Uv[off][1]={0,0};
        for (int m=1;m<=l;m++) {
            double sg = (m&1)?-1.0:1.0;
            Un[off+m]=2;
            Uc[off+m][0]=off+m; Uv[off+m][0]={sg*s2,0};
            Uc[off+m][1]=off-m; Uv[off+m][1]={s2,0};
            Un[off-m]=2;
            Uc[off-m][0]=off-m; Uv[off-m][0]={0,s2};
            Uc[off-m][1]=off+m; Uv[off-m][1]={0,-sg*s2};
        }
    }

    std::vector<Rent> es; es.reserve(5000);
    for (int i=0;i<25;i++)
        for (int j=0;j<25;j++)
            for (int k=0;k<25;k++) {
                std::complex<double> T(0,0);
                for (int a=0;a<Un[i];a++)
                    for (int b=0;b<Un[j];b++)
                        for (int c=0;c<Un[k];c++)
                            T += Uv[i][a]*Uv[j][b]*std::conj(Uv[k][c])*Cc[Uc[i][a]][Uc[j][b]][Uc[k][c]];
                double C = T.real() + T.imag();
                if (std::fabs(C) < 1e-12) continue;
                int p = pid[degof(i)][degof(j)][degof(k)];
                if (p < 0) continue;
                es.push_back({p, k, i, j, C});
            }

    std::sort(es.begin(), es.end(), [](const Rent&a, const Rent&b){
        if (a.path!=b.path) return a.path<b.path;
        if (a.ic!=b.ic) return a.ic<b.ic;
        if (a.ia!=b.ia) return a.ia<b.ia;
        return a.ib<b.ib; });

    nent = (int)std::min((size_t)MAXE, es.size());
    for (int e=0;e<nent;e++) {
        const Rent& r = es[e];
        int s = (degof(r.ia)+degof(r.ib)+degof(r.ic)) & 1;
        h_idx[e] = (unsigned)r.ia | ((unsigned)r.ib<<5) | ((unsigned)r.ic<<10)
                 | ((unsigned)r.path<<15) | ((unsigned)s<<22);
        h_val[e] = (float)r.v;
    }
}
} // namespace tab

// ------------------------- kernels -----------------------------------------
__global__ void zero_kernel(int n) {
    int i = blockIdx.x*blockDim.x + threadIdx.x;
    if (i < n) g_Y0[i] = 0.0f;
}

__global__ __launch_bounds__(256) void edge_kernel(
    const int* __restrict__ an, const int* __restrict__ nbr,
    const float* __restrict__ disp, const float* __restrict__ Wsp,
    const float* __restrict__ norm, int E)
{
    __shared__ float sYe[8][32];
    __shared__ float sG[8][16];
    int w = threadIdx.x >> 5, lane = threadIdx.x & 31;
    int e = blockIdx.x*8 + w;
    if (e >= E) return;

    int i = __ldg(nbr + 2*e), j = __ldg(nbr + 2*e + 1);
    float dx = __ldg(disp+3*e), dy = __ldg(disp+3*e+1), dz = __ldg(disp+3*e+2);
    float r = sqrtf(dx*dx + dy*dy + dz*dz + 1e-12f);
    float inv = 1.0f/r;
    float x = dx*inv, y = dy*inv, z = dz*inv;

    float t = fminf(r*0.2f, 1.0f);
    float fc = 0.5f*(cosf(3.14159265358979f*t) + 1.0f);
    float rb = 0.0f;
    if (lane < 16) {
        float d = r - (float)lane*(1.0f/3.0f);
        rb = __expf(-10.24f*d*d)*fc;
    }

    int Z = __ldg(an + j);
    const float* Wr = Wsp + (size_t)Z*256;
    float g = 0.0f;
    #pragma unroll
    for (int k=0;k<16;k++) {
        float rk = __shfl_sync(0xffffffffu, rb, k);
        float wv = (lane<16) ? __ldg(Wr + k*16 + lane) : 0.0f;
        g = fmaf(rk, wv, g);
    }
    if (lane < 16) sG[w][lane] = g / __ldg(norm);

    float x2=x*x, y2=y*y, z2=z*z;
    if (lane == 0) {
        float* S = sYe[w];
        S[0]=0.28209479177387814f;
        S[1]=0.4886025119029199f*y;  S[2]=0.4886025119029199f*z;  S[3]=0.4886025119029199f*x;
        S[4]=1.0925484305920792f*x*y; S[5]=1.0925484305920792f*y*z;
        S[6]=0.31539156525252005f*(3.f*z2-1.f);
        S[7]=1.0925484305920792f*x*z; S[8]=0.5462742152960396f*(x2-y2);
        S[9]=0.5900435899266435f*y*(3.f*x2-y2);
        S[10]=2.890611442640554f*x*y*z;
        S[11]=0.4570457994644658f*y*(5.f*z2-1.f);
        S[12]=0.3731763325901154f*z*(5.f*z2-3.f);
        S[13]=0.4570457994644658f*x*(5.f*z2-1.f);
        S[14]=1.445305721320277f*z*(x2-y2);
        S[15]=0.5900435899266435f*x*(x2-3.f*y2);
        S[16]=2.5033429417967046f*x*y*(x2-y2);
        S[17]=1.7701307697799304f*y*z*(3.f*x2-y2);
        S[18]=0.9461746957575601f*x*y*(7.f*z2-1.f);
        S[19]=0.6690465435572892f*y*z*(7.f*z2-3.f);
        S[20]=0.10578554691520431f*(35.f*z2*z2-30.f*z2+3.f);
        S[21]=0.6690465435572892f*x*z*(7.f*z2-3.f);
        S[22]=0.47308734787878004f*(x2-y2)*(7.f*z2-1.f);
        S[23]=1.7701307697799304f*x*z*(x2-3.f*y2);
        S[24]=0.6258357354491761f*(x2*x2-6.f*x2*y2+y2*y2);
    }
    __syncwarp();

    size_t base = (size_t)i*400;
    #pragma unroll
    for (int it=0; it<13; it++) {
        int tt = lane + it*32;
        if (tt < 400)
            atomicAdd(&g_Y0[base + tt], sYe[w][tt>>4] * sG[w][tt&15]);
    }
}

template<int L, int FIN>
__device__ __forceinline__ void dd_deg(const float* __restrict__ yin,
    float* __restrict__ sa, float* __restrict__ sb,
    const float* __restrict__ W1, const float* __restrict__ W2, int tid)
{
    constexpr int NL = 2*L+1, B = L*L;
    float aA[NL], aB[NL];
    #pragma unroll
    for (int q=0;q<NL;q++){ aA[q]=0.f; aB[q]=0.f; }
    #pragma unroll 4
    for (int f=0; f<FIN; f++) {
        float w1 = __ldg(W1 + (L*FIN+f)*64 + tid);
        float w2 = __ldg(W2 + (L*FIN+f)*64 + tid);
        #pragma unroll
        for (int q=0;q<NL;q++) {
            float yv = yin[(B+q)*FIN + f];
            aA[q] = fmaf(yv, w1, aA[q]);
            aB[q] = fmaf(yv, w2, aB[q]);
        }
    }
    #pragma unroll
    for (int q=0;q<NL;q++) { sa[(B+q)*64+tid] = aA[q]; sb[(B+q)*64+tid] = aB[q]; }
}

template<bool FULL>
__device__ __forceinline__ void tp_run(const float* __restrict__ sha,
    const float* __restrict__ shb, float* __restrict__ shout,
    const float* __restrict__ wp, int tid, int nent)
{
    float accE=0.f, accO=0.f;
    int cur=-1, curPath=-1, curIc=0, curS=0, lastIa=-1;
    float w00=0.f,w01=0.f,w10=0.f,w11=0.f, a0=0.f, a1=0.f;
    for (int e=0; e<nent; e++) {
        unsigned u = c_idx[e];
        float v = c_val[e];
        int ia = u&31, ib = (u>>5)&31, ic = (u>>10)&31;
        int path = (u>>15)&127, s = (u>>22)&1;
        int key = (path<<5) | ic;
        if (key != cur) {
            if (cur >= 0) {
                shout[(curS*25+curIc)*64+tid] += accE;
                if (FULL) shout[((1-curS)*25+curIc)*64+tid] += accO;
            }
            accE=0.f; accO=0.f; curIc=ic; curS=s; cur=key;
            if (path != curPath) {
                curPath = path;
                const float* wq = wp + path*256 + tid;
                w00 = __ldg(wq);
                if (FULL) { w01=__ldg(wq+64); w10=__ldg(wq+128); w11=__ldg(wq+192); }
            }
        }
        if (ia != lastIa) {
            a0 = sha[ia*64+tid];
            if (FULL) a1 = sha[(25+ia)*64+tid];
            lastIa = ia;
        }
        float b0 = shb[ib*64+tid];
        if (FULL) {
            float b1 = shb[(25+ib)*64+tid];
            accE = fmaf(v, w00*(a0*b0) + w11*(a1*b1), accE);
            accO = fmaf(v, w01*(a0*b1) + w10*(a1*b0), accO);
        } else {
            accE = fmaf(v*w00, a0*b0, accE);
        }
    }
    shout[(curS*25+curIc)*64+tid] += accE;
    if (FULL) shout[((1-curS)*25+curIc)*64+tid] += accO;
}

__global__ __launch_bounds__(64) void atom_kernel(
    const int* __restrict__ an,
    const float* __restrict__ emb, const float* __restrict__ W_et,
    const float* __restrict__ b_et,
    const float* __restrict__ t0W1, const float* __restrict__ t0W2,
    const float* __restrict__ t0wp,
    const float* __restrict__ t1W1, const float* __restrict__ t1W2,
    const float* __restrict__ t1wp,
    const float* __restrict__ wfu, float* __restrict__ out, int nent, int N)
{
    extern __shared__ float sm[];
    float* sy0  = sm;           // 400
    float* sa   = sm + 400;     // 3200
    float* sb   = sa + 3200;    // 3200
    float* sy1  = sb + 3200;    // 3200
    float* sy2  = sy1 + 3200;   // 3200
    float* ste  = sy2 + 3200;   // 144
    float* semb = ste + 144;    // 64

    int n = blockIdx.x;
    if (n >= N) return;
    int tid = threadIdx.x;

    for (int t=tid; t<400; t+=64) sy0[t] = g_Y0[(size_t)n*400 + t];
    int Z = __ldg(an + n);
    semb[tid] = __ldg(emb + (size_t)Z*64 + tid);
    __syncthreads();

    // layer 0 (parity-1 input is zero)
    dd_deg<0,16>(sy0, sa, sb, t0W1, t0W2, tid);
    dd_deg<1,16>(sy0, sa, sb, t0W1, t0W2, tid);
    dd_deg<2,16>(sy0, sa, sb, t0W1, t0W2, tid);
    dd_deg<3,16>(sy0, sa, sb, t0W1, t0W2, tid);
    dd_deg<4,16>(sy0, sa, sb, t0W1, t0W2, tid);
    for (int t=tid; t<3200; t+=64) sy1[t] = 0.f;   // own-channel slots only
    tp_run<false>(sa, sb, sy1, t0wp, tid, nent);
    __syncthreads();

    // layer 1 (both parities)
    dd_deg<0,64>(sy1, sa, sb, t1W1, t1W2, tid);
    dd_deg<1,64>(sy1, sa, sb, t1W1, t1W2, tid);
    dd_deg<2,64>(sy1, sa, sb, t1W1, t1W2, tid);
    dd_deg<3,64>(sy1, sa, sb, t1W1, t1W2, tid);
    dd_deg<4,64>(sy1, sa, sb, t1W1, t1W2, tid);
    dd_deg<0,64>(sy1+1600, sa+1600, sb+1600, t1W1+20480, t1W2+20480, tid);
    dd_deg<1,64>(sy1+1600, sa+1600, sb+1600, t1W1+20480, t1W2+20480, tid);
    dd_deg<2,64>(sy1+1600, sa+1600, sb+1600, t1W1+20480, t1W2+20480, tid);
    dd_deg<3,64>(sy1+1600, sa+1600, sb+1600, t1W1+20480, t1W2+20480, tid);
    dd_deg<4,64>(sy1+1600, sa+1600, sb+1600, t1W1+20480, t1W2+20480, tid);
    for (int t=tid; t<3200; t+=64) sy2[t] = 0.f;
    tp_run<true>(sa, sb, sy2, t1wp, tid, nent);

    // te = emb[Z] @ W_et + b_et  (channels tid, 64+tid, 128+tid)
    float t0 = __ldg(b_et+tid), t1 = __ldg(b_et+64+tid);
    float t2 = (tid<16) ? __ldg(b_et+128+tid) : 0.f;
    for (int d=0; d<64; d++) {
        float ed = semb[d];
        t0 = fmaf(ed, __ldg(W_et + d*144 + tid), t0);
        t1 = fmaf(ed, __ldg(W_et + d*144 + 64 + tid), t1);
        if (tid<16) t2 = fmaf(ed, __ldg(W_et + d*144 + 128 + tid), t2);
    }
    ste[tid] = t0; ste[64+tid] = t1;
    if (tid<16) ste[128+tid] = t2;
    __syncthreads();

    // fused epilogue + mish: out = v*(1+tanh(softplus(v))) = v*2w/(w+1), w=(1+e^v)^2
    for (int t=tid; t<7200; t+=64) {
        int p = t/3600, rem = t - p*3600;
        int lm = rem/144, c = rem - lm*144;
        float feat;
        if (c < 16)       feat = p ? 0.f : sy0[lm*16 + c];
        else if (c < 80)  feat = sy1[(p*25+lm)*64 + (c-16)];
        else              feat = sy2[(p*25+lm)*64 + (c-80)];
        int dg = lm>=16?4: lm>=9?3: lm>=4?2: lm>=1?1:0;
        float v = ste[c] * feat * __ldg(wfu + p*720 + dg*144 + c);
        if (p==0 && lm==0) v += ste[c];
        float ev = __expf(v);
        float w1 = 1.f + ev;
        float w  = w1*w1;
        float r  = (v > 20.f) ? 2.f*v : v * __fdividef(2.f*w, w + 1.f);
        out[(size_t)n*7200 + t] = r;
    }
}

// ------------------------- launch ------------------------------------------
extern "C" void kernel_launch(void* const* d_in, const int* in_sizes, int n_in,
                              void* d_out, int out_size)
{
    tab::build();

    const int*   an   = (const int*)d_in[0];
    const int*   nbr  = (const int*)d_in[1];
    const float* disp = (const float*)d_in[2];
    const float* Wsp  = (const float*)d_in[3];
    const float* emb  = (const float*)d_in[4];
    const float* W_et = (const float*)d_in[5];
    const float* b_et = (const float*)d_in[6];
    const float* norm = (const float*)d_in[7];
    const float* t0W1 = (const float*)d_in[8];
    const float* t0W2 = (const float*)d_in[9];
    const float* t0wp = (const float*)d_in[10];
    const float* t1W1 = (const float*)d_in[11];
    const float* t1W2 = (const float*)d_in[12];
    const float* t1wp = (const float*)d_in[13];
    const float* wfu  = (const float*)d_in[14];
    float* out = (float*)d_out;

    int N = in_sizes[0];
    int E = in_sizes[1] / 2;

    cudaMemcpyToSymbolAsync(c_idx, tab::h_idx, tab::nent*sizeof(unsigned int),
                            0, cudaMemcpyHostToDevice, 0);
    cudaMemcpyToSymbolAsync(c_val, tab::h_val, tab::nent*sizeof(float),
                            0, cudaMemcpyHostToDevice, 0);

    int nz = N * 400;
    zero_kernel<<<(nz + 255)/256, 256>>>(nz);
    edge_kernel<<<(E + 7)/8, 256>>>(an, nbr, disp, Wsp, norm, E);

    static bool attr_done = false;
    size_t smem = 13408 * sizeof(float);
    if (!attr_done) {
        cudaFuncSetAttribute(atom_kernel, cudaFuncAttributeMaxDynamicSharedMemorySize,
                             (int)smem);
        attr_done = true;
    }
    atom_kernel<<<N, 64, smem>>>(an, emb, W_et, b_et, t0W1, t0W2, t0wp,
                                 t1W1, t1W2, t1wp, wfu, out, tab::nent, N);
}

// round 6
// speedup vs baseline: 1.9191x; 1.9191x over previous
#include <cuda_runtime.h>
#include <cmath>
#include <cstdint>
#include <complex>
#include <vector>
#include <algorithm>

#define MAXE 7000
#define MAXG 600
#define MAXN 10000

static __device__ float g_Y0[(size_t)MAXN * 400];
static __device__ uint2 g_ent[MAXE];
static __device__ uint2 g_grp[MAXG];
__constant__ int c_sliceStart[5];

// ------------------------- host CG table ----------------------------------
namespace tab {
static int nent = 0, ngrp = 0;
static uint2 h_ent[MAXE];
static uint2 h_grp[MAXG];
static int h_sliceStart[5];
static bool built = false;

static double lf(int n) { return lgamma((double)n + 1.0); }

static double cgc(int l1, int m1, int l2, int m2, int l3, int m3) {
    if (m1 + m2 != m3 || l3 < abs(l1 - l2) || l3 > l1 + l2) return 0.0;
    double pre = 0.5 * (lf(l1+l2-l3) + lf(l1-l2+l3) + lf(-l1+l2+l3) - lf(l1+l2+l3+1)
                 + lf(l1+m1) + lf(l1-m1) + lf(l2+m2) + lf(l2-m2) + lf(l3+m3) + lf(l3-m3));
    int kmin = std::max(0, std::max(l2-l3-m1, l1-l3+m2));
    int kmax = std::min(l1+l2-l3, std::min(l1-m1, l2+m2));
    double s = 0.0;
    for (int k = kmin; k <= kmax; k++) {
        double ln = lf(k) + lf(l1+l2-l3-k) + lf(l1-m1-k) + lf(l2+m2-k)
                  + lf(l3-l2+m1+k) + lf(l3-l1-m2+k);
        s += ((k & 1) ? -1.0 : 1.0) * exp(pre - ln);
    }
    return sqrt(2.0*l3+1.0) * s;
}

static int degof(int lm){ return lm>=16?4: lm>=9?3: lm>=4?2: lm>=1?1:0; }

struct Rent { int path, ic, ia, ib; double v; };
static std::complex<double> Cc[25][25][25];

static void build() {
    if (built) return;
    built = true;
    int pid[5][5][5];
    for (int a=0;a<5;a++)for(int b=0;b<5;b++)for(int c=0;c<5;c++) pid[a][b][c]=-1;
    int np = 0;
    for (int l1=0;l1<=4;l1++)
        for (int l2=0;l2<=4;l2++)
            for (int l3=abs(l1-l2); l3<=std::min(4,l1+l2); l3++)
                pid[l1][l2][l3] = np++;

    for (int l1=0;l1<=4;l1++)
        for (int l2=0;l2<=4;l2++)
            for (int l3=abs(l1-l2); l3<=std::min(4,l1+l2); l3++)
                for (int m1=-l1;m1<=l1;m1++)
                    for (int m2=-l2;m2<=l2;m2++) {
                        int m3 = m1+m2;
                        if (abs(m3) <= l3)
                            Cc[l1*l1+l1+m1][l2*l2+l2+m2][l3*l3+l3+m3] = cgc(l1,m1,l2,m2,l3,m3);
                    }

    const double s2 = 1.0/sqrt(2.0);
    std::complex<double> Uv[25][2]; int Uc[25][2]; int Un[25];
    for (int l=0;l<=4;l++) {
        int off = l*l+l;
        Un[off]=1; Uc[off][0]=off; Uv[off][0]={1,0}; Uc[off][1]=off; Uv[off][1]={0,0};
        for (int m=1;m<=l;m++) {
            double sg = (m&1)?-1.0:1.0;
            Un[off+m]=2;
            Uc[off+m][0]=off+m; Uv[off+m][0]={sg*s2,0};
            Uc[off+m][1]=off-m; Uv[off+m][1]={s2,0};
            Un[off-m]=2;
            Uc[off-m][0]=off-m; Uv[off-m][0]={0,s2};
            Uc[off-m][1]=off+m; Uv[off-m][1]={0,-sg*s2};
        }
    }

    std::vector<Rent> es; es.reserve(5000);
    for (int i=0;i<25;i++)
        for (int j=0;j<25;j++)
            for (int k=0;k<25;k++) {
                std::complex<double> T(0,0);
                for (int a=0;a<Un[i];a++)
                    for (int b=0;b<Un[j];b++)
                        for (int c=0;c<Un[k];c++)
                            T += Uv[i][a]*Uv[j][b]*std::conj(Uv[k][c])*Cc[Uc[i][a]][Uc[j][b]][Uc[k][c]];
                double C = T.real() + T.imag();
                if (std::fabs(C) < 1e-12) continue;
                int p = pid[degof(i)][degof(j)][degof(k)];
                if (p < 0) continue;
                es.push_back({p, k, i, j, C});
            }

    std::sort(es.begin(), es.end(), [](const Rent&a, const Rent&b){
        if (a.path!=b.path) return a.path<b.path;
        if (a.ic!=b.ic) return a.ic<b.ic;
        if (a.ia!=b.ia) return a.ia<b.ia;
        return a.ib<b.ib; });

    nent = (int)std::min((size_t)MAXE, es.size());
    for (int e=0;e<nent;e++) {
        h_ent[e].x = (unsigned)(es[e].ia*64) | ((unsigned)(es[e].ib*64)<<16);
        float vv = (float)es[e].v;
        unsigned vb; memcpy(&vb, &vv, 4);
        h_ent[e].y = vb;
    }

    // groups on (path, ic) boundaries
    std::vector<int> gstart, gcnt, gic, gss, gpath;
    int lastp=-1, lastic=-1;
    for (int e=0;e<nent;e++) {
        if (es[e].path!=lastp || es[e].ic!=lastic) {
            lastp = es[e].path; lastic = es[e].ic;
            gstart.push_back(e); gcnt.push_back(0);
            gic.push_back(es[e].ic);
            gss.push_back((degof(es[e].ia)+degof(es[e].ib)+degof(es[e].ic))&1);
            gpath.push_back(es[e].path);
        }
        gcnt.back()++;
    }
    int NG = (int)gstart.size();

    // greedy slice assignment (min-loaded)
    std::vector<int> sl(NG); int load[4]={0,0,0,0};
    for (int g=0; g<NG; g++) {
        int m=0;
        for (int k=1;k<4;k++) if (load[k]<load[m]) m=k;
        sl[g]=m; load[m]+=gcnt[g];
    }
    int pos=0;
    for (int s=0;s<4;s++) {
        h_sliceStart[s]=pos;
        for (int g=0; g<NG && pos<MAXG; g++) if (sl[g]==s) {
            h_grp[pos].x = (unsigned)gstart[g] | ((unsigned)gcnt[g]<<16);
            h_grp[pos].y = (unsigned)gic[g] | ((unsigned)gss[g]<<5) | ((unsigned)gpath[g]<<8);
            pos++;
        }
    }
    h_sliceStart[4]=pos; ngrp=pos;
}
} // namespace tab

// ------------------------- edge kernel --------------------------------------
__global__ __launch_bounds__(256) void edge_kernel(
    const int* __restrict__ an, const int* __restrict__ nbr,
    const float* __restrict__ disp, const float* __restrict__ Wsp,
    const float* __restrict__ norm, int E)
{
    __shared__ float sYe[8][32];
    __shared__ float sG[8][16];
    int w = threadIdx.x >> 5, lane = threadIdx.x & 31;
    int e = blockIdx.x*8 + w;
    if (e >= E) return;

    int i = __ldg(nbr + 2*e), j = __ldg(nbr + 2*e + 1);
    float dx = __ldg(disp+3*e), dy = __ldg(disp+3*e+1), dz = __ldg(disp+3*e+2);
    float r = sqrtf(dx*dx + dy*dy + dz*dz + 1e-12f);
    float inv = 1.0f/r;
    float x = dx*inv, y = dy*inv, z = dz*inv;

    float t = fminf(r*0.2f, 1.0f);
    float fc = 0.5f*(cosf(3.14159265358979f*t) + 1.0f);
    float rb = 0.0f;
    if (lane < 16) {
        float d = r - (float)lane*(1.0f/3.0f);
        rb = __expf(-10.24f*d*d)*fc;
    }

    int Z = __ldg(an + j);
    const float* Wr = Wsp + (size_t)Z*256;
    float g = 0.0f;
    #pragma unroll
    for (int k=0;k<16;k++) {
        float rk = __shfl_sync(0xffffffffu, rb, k);
        float wv = (lane<16) ? __ldg(Wr + k*16 + lane) : 0.0f;
        g = fmaf(rk, wv, g);
    }
    if (lane < 16) sG[w][lane] = g / __ldg(norm);

    float x2=x*x, y2=y*y, z2=z*z;
    if (lane == 0) {
        float* S = sYe[w];
        S[0]=0.28209479177387814f;
        S[1]=0.4886025119029199f*y;  S[2]=0.4886025119029199f*z;  S[3]=0.4886025119029199f*x;
        S[4]=1.0925484305920792f*x*y; S[5]=1.0925484305920792f*y*z;
        S[6]=0.31539156525252005f*(3.f*z2-1.f);
        S[7]=1.0925484305920792f*x*z; S[8]=0.5462742152960396f*(x2-y2);
        S[9]=0.5900435899266435f*y*(3.f*x2-y2);
        S[10]=2.890611442640554f*x*y*z;
        S[11]=0.4570457994644658f*y*(5.f*z2-1.f);
        S[12]=0.3731763325901154f*z*(5.f*z2-3.f);
        S[13]=0.4570457994644658f*x*(5.f*z2-1.f);
        S[14]=1.445305721320277f*z*(x2-y2);
        S[15]=0.5900435899266435f*x*(x2-3.f*y2);
        S[16]=2.5033429417967046f*x*y*(x2-y2);
        S[17]=1.7701307697799304f*y*z*(3.f*x2-y2);
        S[18]=0.9461746957575601f*x*y*(7.f*z2-1.f);
        S[19]=0.6690465435572892f*y*z*(7.f*z2-3.f);
        S[20]=0.10578554691520431f*(35.f*z2*z2-30.f*z2+3.f);
        S[21]=0.6690465435572892f*x*z*(7.f*z2-3.f);
        S[22]=0.47308734787878004f*(x2-y2)*(7.f*z2-1.f);
        S[23]=1.7701307697799304f*x*z*(x2-3.f*y2);
        S[24]=0.6258357354491761f*(x2*x2-6.f*x2*y2+y2*y2);
    }
    __syncwarp();

    size_t base = (size_t)i*400;
    #pragma unroll
    for (int it=0; it<13; it++) {
        int tt = lane + it*32;
        if (tt < 400)
            atomicAdd(&g_Y0[base + tt], sYe[w][tt>>4] * sG[w][tt&15]);
    }
}

// ------------------------- atom kernel pieces -------------------------------
// degree_dense partial: this slice covers FIN/4 input channels starting at f0.
// W1/W2 already offset to (parity, L) block; yin/sa/sb offset to parity block.
template<int L, int FIN>
__device__ __forceinline__ void dd_part(const float* __restrict__ yin,
    float* __restrict__ sa, float* __restrict__ sb,
    const float* __restrict__ W1, const float* __restrict__ W2,
    int ch, int f0)
{
    constexpr int NL = 2*L+1, B = L*L;
    float aA[NL], aB[NL];
    #pragma unroll
    for (int q=0;q<NL;q++){ aA[q]=0.f; aB[q]=0.f; }
    #pragma unroll 4
    for (int f=f0; f<f0+FIN/4; f++) {
        float w1 = __ldg(W1 + f*64 + ch);
        float w2 = __ldg(W2 + f*64 + ch);
        #pragma unroll
        for (int q=0;q<NL;q++) {
            float yv = yin[(B+q)*FIN + f];
            aA[q] = fmaf(yv, w1, aA[q]);
            aB[q] = fmaf(yv, w2, aB[q]);
        }
    }
    #pragma unroll
    for (int q=0;q<NL;q++) {
        atomicAdd(&sa[(B+q)*64+ch], aA[q]);
        atomicAdd(&sb[(B+q)*64+ch], aB[q]);
    }
}

// sparse CG tensor product over this slice's groups
template<bool FULL>
__device__ __forceinline__ void tp_run(const float* __restrict__ sha,
    const float* __restrict__ shb, float* __restrict__ shout,
    const float* __restrict__ wp, int ch, int g0, int g1)
{
    for (int gi=g0; gi<g1; gi++) {
        uint2 G = __ldg(&g_grp[gi]);
        int start = G.x & 0xFFFF, cnt = (int)(G.x >> 16);
        int ic = G.y & 31, s = (G.y>>5)&1, path = (int)(G.y>>8);
        const float* wq = wp + path*256 + ch;
        float w00 = __ldg(wq), w01=0.f, w10=0.f, w11=0.f;
        if (FULL){ w01=__ldg(wq+64); w10=__ldg(wq+128); w11=__ldg(wq+192); }
        float accE=0.f, accO=0.f;
        for (int k=0;k<cnt;k++){
            uint2 E = __ldg(&g_ent[start+k]);
            int iao = E.x & 0xFFFF, ibo = (int)(E.x>>16);
            float v = __uint_as_float(E.y);
            float a0 = sha[iao+ch], b0 = shb[ibo+ch];
            if (FULL){
                float a1 = sha[iao+1600+ch], b1 = shb[ibo+1600+ch];
                accE = fmaf(v, w00*(a0*b0)+w11*(a1*b1), accE);
                accO = fmaf(v, w01*(a0*b1)+w10*(a1*b0), accO);
            } else {
                accE = fmaf(v*w00, a0*b0, accE);
            }
        }
        atomicAdd(&shout[(s*25+ic)*64+ch], accE);
        if (FULL) atomicAdd(&shout[((1-s)*25+ic)*64+ch], accO);
    }
}

__global__ __launch_bounds__(256, 4) void atom_kernel(
    const int* __restrict__ an,
    const float* __restrict__ emb, const float* __restrict__ W_et,
    const float* __restrict__ b_et,
    const float* __restrict__ t0W1, const float* __restrict__ t0W2,
    const float* __restrict__ t0wp,
    const float* __restrict__ t1W1, const float* __restrict__ t1W2,
    const float* __restrict__ t1wp,
    const float* __restrict__ wfu, float* __restrict__ out, int N)
{
    extern __shared__ float sm[];
    float* sy0  = sm;           // 400
    float* sa   = sm + 400;     // 3200
    float* sb   = sa + 3200;    // 3200
    float* sy1  = sb + 3200;    // 3200
    float* sy2  = sy1 + 3200;   // 3200
    float* ste  = sy2 + 3200;   // 144
    float* semb = ste + 144;    // 64

    int n = blockIdx.x;
    if (n >= N) return;
    int tid = threadIdx.x;
    int ch = tid & 63, sl = tid >> 6;
    int g0 = c_sliceStart[sl], g1 = c_sliceStart[sl+1];

    // P1: loads + zero work buffers
    for (int t=tid; t<400; t+=256) sy0[t] = g_Y0[(size_t)n*400 + t];
    if (tid < 64) {
        int Z = __ldg(an + n);
        semb[tid] = __ldg(emb + (size_t)Z*64 + tid);
    }
    for (int t=tid; t<3200; t+=256) { sa[t]=0.f; sb[t]=0.f; sy1[t]=0.f; sy2[t]=0.f; }
    __syncthreads();

    // P2: dd0 (parity-0 only, FIN=16; slice covers 4 input channels) + te
    dd_part<0,16>(sy0, sa, sb, t0W1,        t0W2,        ch, sl*4);
    dd_part<1,16>(sy0, sa, sb, t0W1+1024,   t0W2+1024,   ch, sl*4);
    dd_part<2,16>(sy0, sa, sb, t0W1+2048,   t0W2+2048,   ch, sl*4);
    dd_part<3,16>(sy0, sa, sb, t0W1+3072,   t0W2+3072,   ch, sl*4);
    dd_part<4,16>(sy0, sa, sb, t0W1+4096,   t0W2+4096,   ch, sl*4);
    if (tid < 144) {
        float acc = __ldg(b_et + tid);
        for (int d=0; d<64; d++)
            acc = fmaf(semb[d], __ldg(W_et + d*144 + tid), acc);
        ste[tid] = acc;
    }
    __syncthreads();

    // P3: tp0 (layer-0, odd-parity inputs are zero)
    tp_run<false>(sa, sb, sy1, t0wp, ch, g0, g1);
    __syncthreads();

    // P4: re-zero dd buffers
    for (int t=tid; t<3200; t+=256) { sa[t]=0.f; sb[t]=0.f; }
    __syncthreads();

    // P5: dd1 (both parities, FIN=64; slice covers 16 input channels)
    #pragma unroll
    for (int p=0; p<2; p++) {
        const float* yin = sy1 + p*1600;
        float* sap = sa + p*1600;
        float* sbp = sb + p*1600;
        const float* W1 = t1W1 + p*20480;
        const float* W2 = t1W2 + p*20480;
        dd_part<0,64>(yin, sap, sbp, W1,         W2,         ch, sl*16);
        dd_part<1,64>(yin, sap, sbp, W1+4096,    W2+4096,    ch, sl*16);
        dd_part<2,64>(yin, sap, sbp, W1+8192,    W2+8192,    ch, sl*16);
        dd_part<3,64>(yin, sap, sbp, W1+12288,   W2+12288,   ch, sl*16);
        dd_part<4,64>(yin, sap, sbp, W1+16384,   W2+16384,   ch, sl*16);
    }
    __syncthreads();

    // P6: tp1 (full)
    tp_run<true>(sa, sb, sy2, t1wp, ch, g0, g1);
    __syncthreads();

    // P7: fused epilogue + mish: out = v*2w/(w+1), w=(1+e^v)^2
    for (int t=tid; t<7200; t+=256) {
        int p = t/3600, rem = t - p*3600;
        int lm = rem/144, c = rem - lm*144;
        float feat;
        if (c < 16)       feat = p ? 0.f : sy0[lm*16 + c];
        else if (c < 80)  feat = sy1[(p*25+lm)*64 + (c-16)];
        else              feat = sy2[(p*25+lm)*64 + (c-80)];
        int dg = lm>=16?4: lm>=9?3: lm>=4?2: lm>=1?1:0;
        float v = ste[c] * feat * __ldg(wfu + p*720 + dg*144 + c);
        if (p==0 && lm==0) v += ste[c];
        float ev = __expf(v);
        float w1 = 1.f + ev;
        float w  = w1*w1;
        float r  = (v > 20.f) ? 2.f*v : v * __fdividef(2.f*w, w + 1.f);
        out[(size_t)n*7200 + t] = r;
    }
}

// ------------------------- launch ------------------------------------------
extern "C" void kernel_launch(void* const* d_in, const int* in_sizes, int n_in,
                              void* d_out, int out_size)
{
    tab::build();

    const int*   an   = (const int*)d_in[0];
    const int*   nbr  = (const int*)d_in[1];
    const float* disp = (const float*)d_in[2];
    const float* Wsp  = (const float*)d_in[3];
    const float* emb  = (const float*)d_in[4];
    const float* W_et = (const float*)d_in[5];
    const float* b_et = (const float*)d_in[6];
    const float* norm = (const float*)d_in[7];
    const float* t0W1 = (const float*)d_in[8];
    const float* t0W2 = (const float*)d_in[9];
    const float* t0wp = (const float*)d_in[10];
    const float* t1W1 = (const float*)d_in[11];
    const float* t1W2 = (const float*)d_in[12];
    const float* t1wp = (const float*)d_in[13];
    const float* wfu  = (const float*)d_in[14];
    float* out = (float*)d_out;

    int N = in_sizes[0];
    int E = in_sizes[1] / 2;

    cudaMemcpyToSymbolAsync(g_ent, tab::h_ent, tab::nent*sizeof(uint2),
                            0, cudaMemcpyHostToDevice, 0);
    cudaMemcpyToSymbolAsync(g_grp, tab::h_grp, tab::ngrp*sizeof(uint2),
                            0, cudaMemcpyHostToDevice, 0);
    cudaMemcpyToSymbolAsync(c_sliceStart, tab::h_sliceStart, 5*sizeof(int),
                            0, cudaMemcpyHostToDevice, 0);

    void* y0ptr = nullptr;
    cudaGetSymbolAddress(&y0ptr, g_Y0);
    cudaMemsetAsync(y0ptr, 0, (size_t)N*400*sizeof(float), 0);

    edge_kernel<<<(E + 7)/8, 256>>>(an, nbr, disp, Wsp, norm, E);

    static bool attr_done = false;
    size_t smem = 13408 * sizeof(float);
    if (!attr_done) {
        cudaFuncSetAttribute(atom_kernel, cudaFuncAttributeMaxDynamicSharedMemorySize,
                             (int)smem);
        attr_done = true;
    }
    atom_kernel<<<N, 256, smem>>>(an, emb, W_et, b_et, t0W1, t0W2, t0wp,
                                  t1W1, t1W2, t1wp, wfu, out, N);
}

// round 7
// speedup vs baseline: 2.4642x; 1.2840x over previous
#include <cuda_runtime.h>
#include <cmath>
#include <cstdint>
#include <cstring>
#include <complex>
#include <vector>
#include <algorithm>

#define MAXE 7000
#define MAXG 600
#define MAXN 10000
#define NSLICE 8

static __device__ float g_Y0[(size_t)MAXN * 400];
static __device__ uint2 g_ent[MAXE];
static __device__ uint2 g_grp[MAXG];
__constant__ int c_sliceStart[NSLICE + 1];

typedef unsigned long long ull;

// f32x2 packed math (FFMA2/FMUL2 — PTX-only on sm_103a)
#define FMA2(d, a, b, c) asm("fma.rn.f32x2 %0, %1, %2, %3;" : "=l"(d) : "l"(a), "l"(b), "l"(c))
#define MUL2(d, a, b)    asm("mul.rn.f32x2 %0, %1, %2;"     : "=l"(d) : "l"(a), "l"(b))
#define SPLAT2(d, s)     asm("mov.b64 %0, {%1, %1};"        : "=l"(d) : "r"(s))

__device__ __forceinline__ ull ld2s(const float* p) {            // LDS.64
    return *(const ull*)p;
}
__device__ __forceinline__ ull ld2g(const float* p) {            // LDG.64
    return __ldg((const ull*)p);
}
__device__ __forceinline__ float2 unp(ull v) {
    float2 f; memcpy(&f, &v, 8); return f;
}

// ------------------------- host CG table ----------------------------------
namespace tab {
static int nent = 0, ngrp = 0;
static uint2 h_ent[MAXE];
static uint2 h_grp[MAXG];
static int h_sliceStart[NSLICE + 1];
static bool built = false;

static double lf(int n) { return lgamma((double)n + 1.0); }

static double cgc(int l1, int m1, int l2, int m2, int l3, int m3) {
    if (m1 + m2 != m3 || l3 < abs(l1 - l2) || l3 > l1 + l2) return 0.0;
    double pre = 0.5 * (lf(l1+l2-l3) + lf(l1-l2+l3) + lf(-l1+l2+l3) - lf(l1+l2+l3+1)
                 + lf(l1+m1) + lf(l1-m1) + lf(l2+m2) + lf(l2-m2) + lf(l3+m3) + lf(l3-m3));
    int kmin = std::max(0, std::max(l2-l3-m1, l1-l3+m2));
    int kmax = std::min(l1+l2-l3, std::min(l1-m1, l2+m2));
    double s = 0.0;
    for (int k = kmin; k <= kmax; k++) {
        double ln = lf(k) + lf(l1+l2-l3-k) + lf(l1-m1-k) + lf(l2+m2-k)
                  + lf(l3-l2+m1+k) + lf(l3-l1-m2+k);
        s += ((k & 1) ? -1.0 : 1.0) * exp(pre - ln);
    }
    return sqrt(2.0*l3+1.0) * s;
}

static int degof(int lm){ return lm>=16?4: lm>=9?3: lm>=4?2: lm>=1?1:0; }

struct Rent { int path, ic, ia, ib; double v; };
static std::complex<double> Cc[25][25][25];

static void build() {
    if (built) return;
    built = true;
    int pid[5][5][5];
    for (int a=0;a<5;a++)for(int b=0;b<5;b++)for(int c=0;c<5;c++) pid[a][b][c]=-1;
    int np = 0;
    for (int l1=0;l1<=4;l1++)
        for (int l2=0;l2<=4;l2++)
            for (int l3=abs(l1-l2); l3<=std::min(4,l1+l2); l3++)
                pid[l1][l2][l3] = np++;

    for (int l1=0;l1<=4;l1++)
        for (int l2=0;l2<=4;l2++)
            for (int l3=abs(l1-l2); l3<=std::min(4,l1+l2); l3++)
                for (int m1=-l1;m1<=l1;m1++)
                    for (int m2=-l2;m2<=l2;m2++) {
                        int m3 = m1+m2;
                        if (abs(m3) <= l3)
                            Cc[l1*l1+l1+m1][l2*l2+l2+m2][l3*l3+l3+m3] = cgc(l1,m1,l2,m2,l3,m3);
                    }

    const double s2 = 1.0/sqrt(2.0);
    std::complex<double> Uv[25][2]; int Uc[25][2]; int Un[25];
    for (int l=0;l<=4;l++) {
        int off = l*l+l;
        Un[off]=1; Uc[off][0]=off; Uv[off][0]={1,0}; Uc[off][1]=off; Uv[off][1]={0,0};
        for (int m=1;m<=l;m++) {
            double sg = (m&1)?-1.0:1.0;
            Un[off+m]=2;
            Uc[off+m][0]=off+m; Uv[off+m][0]={sg*s2,0};
            Uc[off+m][1]=off-m; Uv[off+m][1]={s2,0};
            Un[off-m]=2;
            Uc[off-m][0]=off-m; Uv[off-m][0]={0,s2};
            Uc[off-m][1]=off+m; Uv[off-m][1]={0,-sg*s2};
        }
    }

    std::vector<Rent> es; es.reserve(5000);
    for (int i=0;i<25;i++)
        for (int j=0;j<25;j++)
            for (int k=0;k<25;k++) {
                std::complex<double> T(0,0);
                for (int a=0;a<Un[i];a++)
                    for (int b=0;b<Un[j];b++)
                        for (int c=0;c<Un[k];c++)
                            T += Uv[i][a]*Uv[j][b]*std::conj(Uv[k][c])*Cc[Uc[i][a]][Uc[j][b]][Uc[k][c]];
                double C = T.real() + T.imag();
                if (std::fabs(C) < 1e-12) continue;
                int p = pid[degof(i)][degof(j)][degof(k)];
                if (p < 0) continue;
                es.push_back({p, k, i, j, C});
            }

    std::sort(es.begin(), es.end(), [](const Rent&a, const Rent&b){
        if (a.path!=b.path) return a.path<b.path;
        if (a.ic!=b.ic) return a.ic<b.ic;
        if (a.ia!=b.ia) return a.ia<b.ia;
        return a.ib<b.ib; });

    nent = (int)std::min((size_t)MAXE, es.size());
    for (int e=0;e<nent;e++) {
        // offsets premultiplied for [lm][parity][64ch] layout (128 floats per lm)
        h_ent[e].x = (unsigned)(es[e].ia*128) | ((unsigned)(es[e].ib*128)<<16);
        float vv = (float)es[e].v;
        unsigned vb; memcpy(&vb, &vv, 4);
        h_ent[e].y = vb;
    }

    // groups on (path, ic) boundaries
    std::vector<int> gstart, gcnt, gic, gss, gpath;
    int lastp=-1, lastic=-1;
    for (int e=0;e<nent;e++) {
        if (es[e].path!=lastp || es[e].ic!=lastic) {
            lastp = es[e].path; lastic = es[e].ic;
            gstart.push_back(e); gcnt.push_back(0);
            gic.push_back(es[e].ic);
            gss.push_back((degof(es[e].ia)+degof(es[e].ib)+degof(es[e].ic))&1);
            gpath.push_back(es[e].path);
        }
        gcnt.back()++;
    }
    int NG = (int)gstart.size();

    // greedy slice assignment over NSLICE warps
    std::vector<int> ord(NG);
    for (int g=0; g<NG; g++) ord[g]=g;
    std::sort(ord.begin(), ord.end(), [&](int a, int b){ return gcnt[a]>gcnt[b]; });
    std::vector<int> sl(NG); long load[NSLICE]={0};
    for (int oi=0; oi<NG; oi++) {
        int g = ord[oi];
        int m=0;
        for (int k=1;k<NSLICE;k++) if (load[k]<load[m]) m=k;
        sl[g]=m; load[m]+=gcnt[g]+4;
    }
    int pos=0;
    for (int s=0;s<NSLICE;s++) {
        h_sliceStart[s]=pos;
        for (int g=0; g<NG && pos<MAXG; g++) if (sl[g]==s) {
            h_grp[pos].x = (unsigned)gstart[g] | ((unsigned)gcnt[g]<<16);
            h_grp[pos].y = (unsigned)gic[g] | ((unsigned)gss[g]<<5) | ((unsigned)gpath[g]<<8);
            pos++;
        }
    }
    h_sliceStart[NSLICE]=pos; ngrp=pos;
}
} // namespace tab

// ------------------------- edge kernel --------------------------------------
__global__ __launch_bounds__(256) void edge_kernel(
    const int* __restrict__ an, const int* __restrict__ nbr,
    const float* __restrict__ disp, const float* __restrict__ Wsp,
    const float* __restrict__ norm, int E)
{
    __shared__ float sYe[8][32];
    __shared__ float sG[8][16];
    int w = threadIdx.x >> 5, lane = threadIdx.x & 31;
    int e = blockIdx.x*8 + w;
    if (e >= E) return;

    int i = __ldg(nbr + 2*e), j = __ldg(nbr + 2*e + 1);
    float dx = __ldg(disp+3*e), dy = __ldg(disp+3*e+1), dz = __ldg(disp+3*e+2);
    float r = sqrtf(dx*dx + dy*dy + dz*dz + 1e-12f);
    float inv = 1.0f/r;
    float x = dx*inv, y = dy*inv, z = dz*inv;

    float t = fminf(r*0.2f, 1.0f);
    float fc = 0.5f*(cosf(3.14159265358979f*t) + 1.0f);
    float rb = 0.0f;
    if (lane < 16) {
        float d = r - (float)lane*(1.0f/3.0f);
        rb = __expf(-10.24f*d*d)*fc;
    }

    int Z = __ldg(an + j);
    const float* Wr = Wsp + (size_t)Z*256;
    float g = 0.0f;
    #pragma unroll
    for (int k=0;k<16;k++) {
        float rk = __shfl_sync(0xffffffffu, rb, k);
        float wv = (lane<16) ? __ldg(Wr + k*16 + lane) : 0.0f;
        g = fmaf(rk, wv, g);
    }
    if (lane < 16) sG[w][lane] = g / __ldg(norm);

    float x2=x*x, y2=y*y, z2=z*z;
    if (lane == 0) {
        float* S = sYe[w];
        S[0]=0.28209479177387814f;
        S[1]=0.4886025119029199f*y;  S[2]=0.4886025119029199f*z;  S[3]=0.4886025119029199f*x;
        S[4]=1.0925484305920792f*x*y; S[5]=1.0925484305920792f*y*z;
        S[6]=0.31539156525252005f*(3.f*z2-1.f);
        S[7]=1.0925484305920792f*x*z; S[8]=0.5462742152960396f*(x2-y2);
        S[9]=0.5900435899266435f*y*(3.f*x2-y2);
        S[10]=2.890611442640554f*x*y*z;
        S[11]=0.4570457994644658f*y*(5.f*z2-1.f);
        S[12]=0.3731763325901154f*z*(5.f*z2-3.f);
        S[13]=0.4570457994644658f*x*(5.f*z2-1.f);
        S[14]=1.445305721320277f*z*(x2-y2);
        S[15]=0.5900435899266435f*x*(x2-3.f*y2);
        S[16]=2.5033429417967046f*x*y*(x2-y2);
        S[17]=1.7701307697799304f*y*z*(3.f*x2-y2);
        S[18]=0.9461746957575601f*x*y*(7.f*z2-1.f);
        S[19]=0.6690465435572892f*y*z*(7.f*z2-3.f);
        S[20]=0.10578554691520431f*(35.f*z2*z2-30.f*z2+3.f);
        S[21]=0.6690465435572892f*x*z*(7.f*z2-3.f);
        S[22]=0.47308734787878004f*(x2-y2)*(7.f*z2-1.f);
        S[23]=1.7701307697799304f*x*z*(x2-3.f*y2);
        S[24]=0.6258357354491761f*(x2*x2-6.f*x2*y2+y2*y2);
    }
    __syncwarp();

    size_t base = (size_t)i*400;
    #pragma unroll
    for (int it=0; it<13; it++) {
        int tt = lane + it*32;
        if (tt < 400)
            atomicAdd(&g_Y0[base + tt], sYe[w][tt>>4] * sG[w][tt&15]);
    }
}

// ------------------------- atom kernel --------------------------------------
// Layouts (floats):
//  sy0  [25][16]                 (y0, parity0 only; layer-0 input, R=16 channels)
//  sa   [25 lm][2 parity][64 ch] (degree_dense output A)   3200
//  sb   same                                               3200
//  sy1  [25 lm][2 parity][64 ch] (layer-0 TP output)       3200
//  sy2  same (layer-1 TP output)                           3200
//  ste  [144], semb [64]
__global__ __launch_bounds__(256, 4) void atom_kernel(
    const int* __restrict__ an,
    const float* __restrict__ emb, const float* __restrict__ W_et,
    const float* __restrict__ b_et,
    const float* __restrict__ t0W1, const float* __restrict__ t0W2,
    const float* __restrict__ t0wp,
    const float* __restrict__ t1W1, const float* __restrict__ t1W2,
    const float* __restrict__ t1wp,
    const float* __restrict__ wfu, float* __restrict__ out, int N)
{
    extern __shared__ float sm[];
    float* sy0  = sm;           // 400
    float* sa   = sm + 400;     // 3200
    float* sb   = sa + 3200;    // 3200
    float* sy1  = sb + 3200;    // 3200
    float* sy2  = sy1 + 3200;   // 3200
    float* ste  = sy2 + 3200;   // 144
    float* semb = ste + 144;    // 64

    int n = blockIdx.x;
    if (n >= N) return;
    int tid = threadIdx.x;
    int w = tid >> 5, lane = tid & 31;
    int lane2 = lane * 2;                  // this lane owns channels lane2, lane2+1

    // ---- P1: loads + zero TP output buffers ----
    for (int t = tid; t < 400; t += 256) sy0[t] = g_Y0[(size_t)n*400 + t];
    if (tid < 64) {
        int Z = __ldg(an + n);
        semb[tid] = __ldg(emb + (size_t)Z*64 + tid);
    }
    for (int t = tid; t < 3200; t += 256) { sy1[t] = 0.f; sy2[t] = 0.f; }
    __syncthreads();

    // ---- P2: dd0 (row-split, parity0, FIN=16) + te ----
    // rows = lm 0..24; warp w takes lm = w, w+8, w+16
    for (int lm = w; lm < 25; lm += NSLICE) {
        int L = lm>=16?4: lm>=9?3: lm>=4?2: lm>=1?1:0;
        const float* W1 = t0W1 + L*1024 + lane2;     // [L][f][64]
        const float* W2 = t0W2 + L*1024 + lane2;
        const float* yrow = sy0 + lm*16;
        ull aA = 0, aB = 0;
        #pragma unroll
        for (int f = 0; f < 16; f++) {
            ull yy; SPLAT2(yy, __float_as_uint(yrow[f]));
            ull w1 = ld2g(W1 + f*64);
            ull w2 = ld2g(W2 + f*64);
            FMA2(aA, yy, w1, aA);
            FMA2(aB, yy, w2, aB);
        }
        *(ull*)&sa[lm*128 + lane2] = aA;    // parity0 slot
        *(ull*)&sb[lm*128 + lane2] = aB;
    }
    if (tid < 144) {
        float acc = __ldg(b_et + tid);
        #pragma unroll 8
        for (int d = 0; d < 64; d++)
            acc = fmaf(semb[d], __ldg(W_et + d*144 + tid), acc);
        ste[tid] = acc;
    }
    __syncthreads();

    // ---- P3: tp0 (layer 0, only parity-0 inputs nonzero) ----
    {
        int g0 = c_sliceStart[w], g1 = c_sliceStart[w+1];
        for (int gi = g0; gi < g1; gi++) {
            uint2 G = __ldg(&g_grp[gi]);
            int start = G.x & 0xFFFF, cnt = (int)(G.x >> 16);
            int ic = G.y & 31, s = (G.y>>5)&1, path = (int)(G.y>>8);
            ull s00 = 0;
            for (int k = 0; k < cnt; k++) {
                uint2 Ee = __ldg(&g_ent[start+k]);
                const float* A = sa + (Ee.x & 0xFFFF) + lane2;
                const float* B = sb + (Ee.x >> 16) + lane2;
                ull a0 = ld2s(A), b0 = ld2s(B);
                ull vv; SPLAT2(vv, Ee.y);
                ull p00; MUL2(p00, a0, b0);
                FMA2(s00, vv, p00, s00);
            }
            float2 t00 = unp(s00);
            float2 w00 = *(const float2*)(t0wp + path*256 + lane2);
            atomicAdd(&sy1[ic*128 + s*64 + lane2],     w00.x * t00.x);
            atomicAdd(&sy1[ic*128 + s*64 + lane2 + 1], w00.y * t00.y);
        }
    }
    __syncthreads();

    // ---- P4: dd1 (row-split, both parities, FIN=64) ----
    // rows r = 0..49: p = r/25, lm = r%25; warp w takes r = w, w+8, ...
    for (int r = w; r < 50; r += NSLICE) {
        int p = (r >= 25), lm = r - p*25;
        int L = lm>=16?4: lm>=9?3: lm>=4?2: lm>=1?1:0;
        const float* W1 = t1W1 + p*20480 + L*4096 + lane2;   // [p][L][f][64]
        const float* W2 = t1W2 + p*20480 + L*4096 + lane2;
        const float* yrow = sy1 + lm*128 + p*64;
        ull aA = 0, aB = 0;
        #pragma unroll 8
        for (int f = 0; f < 64; f++) {
            ull yy; SPLAT2(yy, __float_as_uint(yrow[f]));
            ull w1 = ld2g(W1 + f*64);
            ull w2 = ld2g(W2 + f*64);
            FMA2(aA, yy, w1, aA);
            FMA2(aB, yy, w2, aB);
        }
        *(ull*)&sa[lm*128 + p*64 + lane2] = aA;
        *(ull*)&sb[lm*128 + p*64 + lane2] = aB;
    }
    __syncthreads();

    // ---- P5: tp1 (full, both parities) ----
    {
        int g0 = c_sliceStart[w], g1 = c_sliceStart[w+1];
        for (int gi = g0; gi < g1; gi++) {
            uint2 G = __ldg(&g_grp[gi]);
            int start = G.x & 0xFFFF, cnt = (int)(G.x >> 16);
            int ic = G.y & 31, s = (G.y>>5)&1, path = (int)(G.y>>8);
            ull s00 = 0, s11 = 0, s01 = 0, s10 = 0;
            for (int k = 0; k < cnt; k++) {
                uint2 Ee = __ldg(&g_ent[start+k]);
                const float* A = sa + (Ee.x & 0xFFFF) + lane2;
                const float* B = sb + (Ee.x >> 16) + lane2;
                ull a0 = ld2s(A), a1 = ld2s(A + 64);
                ull b0 = ld2s(B), b1 = ld2s(B + 64);
                ull vv; SPLAT2(vv, Ee.y);
                ull p00, p11, p01, p10;
                MUL2(p00, a0, b0); MUL2(p11, a1, b1);
                MUL2(p01, a0, b1); MUL2(p10, a1, b0);
                FMA2(s00, vv, p00, s00);
                FMA2(s11, vv, p11, s11);
                FMA2(s01, vv, p01, s01);
                FMA2(s10, vv, p10, s10);
            }
            const float* wq = t1wp + path*256 + lane2;
            float2 w00 = *(const float2*)(wq);
            float2 w01 = *(const float2*)(wq + 64);
            float2 w10 = *(const float2*)(wq + 128);
            float2 w11 = *(const float2*)(wq + 192);
            float2 t00 = unp(s00), t11 = unp(s11), t01 = unp(s01), t10 = unp(s10);
            float evx = fmaf(w00.x, t00.x, w11.x * t11.x);
            float evy = fmaf(w00.y, t00.y, w11.y * t11.y);
            float odx = fmaf(w01.x, t01.x, w10.x * t10.x);
            float ody = fmaf(w01.y, t01.y, w10.y * t10.y);
            atomicAdd(&sy2[ic*128 + s*64 + lane2],         evx);
            atomicAdd(&sy2[ic*128 + s*64 + lane2 + 1],     evy);
            atomicAdd(&sy2[ic*128 + (1-s)*64 + lane2],     odx);
            atomicAdd(&sy2[ic*128 + (1-s)*64 + lane2 + 1], ody);
        }
    }
    __syncthreads();

    // ---- P6: fused epilogue + mish ----
    for (int t = tid; t < 7200; t += 256) {
        int p = t/3600, rem = t - p*3600;
        int lm = rem/144, c = rem - lm*144;
        float feat;
        if (c < 16)       feat = p ? 0.f : sy0[lm*16 + c];
        else if (c < 80)  feat = sy1[lm*128 + p*64 + (c-16)];
        else              feat = sy2[lm*128 + p*64 + (c-80)];
        int dg = lm>=16?4: lm>=9?3: lm>=4?2: lm>=1?1:0;
        float v = ste[c] * feat * __ldg(wfu + p*720 + dg*144 + c);
        if (p==0 && lm==0) v += ste[c];
        float ev = __expf(v);
        float w1v = 1.f + ev;
        float wv  = w1v*w1v;
        float rr  = (v > 20.f) ? 2.f*v : v * __fdividef(2.f*wv, wv + 1.f);
        out[(size_t)n*7200 + t] = rr;
    }
}

// ------------------------- launch ------------------------------------------
extern "C" void kernel_launch(void* const* d_in, const int* in_sizes, int n_in,
                              void* d_out, int out_size)
{
    tab::build();

    const int*   an   = (const int*)d_in[0];
    const int*   nbr  = (const int*)d_in[1];
    const float* disp = (const float*)d_in[2];
    const float* Wsp  = (const float*)d_in[3];
    const float* emb  = (const float*)d_in[4];
    const float* W_et = (const float*)d_in[5];
    const float* b_et = (const float*)d_in[6];
    const float* norm = (const float*)d_in[7];
    const float* t0W1 = (const float*)d_in[8];
    const float* t0W2 = (const float*)d_in[9];
    const float* t0wp = (const float*)d_in[10];
    const float* t1W1 = (const float*)d_in[11];
    const float* t1W2 = (const float*)d_in[12];
    const float* t1wp = (const float*)d_in[13];
    const float* wfu  = (const float*)d_in[14];
    float* out = (float*)d_out;

    int N = in_sizes[0];
    int E = in_sizes[1] / 2;

    cudaMemcpyToSymbolAsync(g_ent, tab::h_ent, tab::nent*sizeof(uint2),
                            0, cudaMemcpyHostToDevice, 0);
    cudaMemcpyToSymbolAsync(g_grp, tab::h_grp, tab::ngrp*sizeof(uint2),
                            0, cudaMemcpyHostToDevice, 0);
    cudaMemcpyToSymbolAsync(c_sliceStart, tab::h_sliceStart, (NSLICE+1)*sizeof(int),
                            0, cudaMemcpyHostToDevice, 0);

    void* y0ptr = nullptr;
    cudaGetSymbolAddress(&y0ptr, g_Y0);
    cudaMemsetAsync(y0ptr, 0, (size_t)N*400*sizeof(float), 0);

    edge_kernel<<<(E + 7)/8, 256>>>(an, nbr, disp, Wsp, norm, E);

    static bool attr_done = false;
    size_t smem = 13408 * sizeof(float);
    if (!attr_done) {
        cudaFuncSetAttribute(atom_kernel, cudaFuncAttributeMaxDynamicSharedMemorySize,
                             (int)smem);
        attr_done = true;
    }
    atom_kernel<<<N, 256, smem>>>(an, emb, W_et, b_et, t0W1, t0W2, t0wp,
                                  t1W1, t1W2, t1wp, wfu, out, N);
}